// round 12
// baseline (speedup 1.0000x reference)
#include <cuda_runtime.h>
#include <cuda_bf16.h>
#include <cstdint>

#define N 8192
#define D 64

// ---- scratch (__device__ globals: the sanctioned no-alloc path) ----
__device__ __nv_bfloat16 g_K[(size_t)N * N];   // 128 MB: K_ij = exp(-C_ij/eps), bf16
__device__ float g_rowpart[256][N];            // 8 MB: per-(coltile,colwarp) row partial sums
__device__ float g_sp[N];
__device__ float g_sq[N];
__device__ float g_u [N];
__device__ float g_v [N];
__device__ float g_part[N];

__device__ __forceinline__ float fsqrt_approx(float x) {
    float r; asm("sqrt.approx.f32 %0, %1;" : "=f"(r) : "f"(x)); return r;
}
__device__ __forceinline__ float fex2_approx(float x) {
    float r; asm("ex2.approx.f32 %0, %1;" : "=f"(r) : "f"(x)); return r;
}
__device__ __forceinline__ float flg2_approx(float x) {
    float r; asm("lg2.approx.f32 %0, %1;" : "=f"(r) : "f"(x)); return r;
}

// -(1/eps) * log2(e),  eps = 0.1
#define NEG_INVEPS_LOG2E (-14.4269504088896340736f)
// -eps * ln(2)  : C = -eps*ln(K) = lg2(K) * (-eps*ln2)
#define NEG_EPS_LN2      (-0.069314718055994530942f)

// ---------------------------------------------------------------------------
// 1) row norms of P and Q  (deterministic per call)
// ---------------------------------------------------------------------------
__global__ void norms_kernel(const float* __restrict__ P, const float* __restrict__ Q) {
    int row  = blockIdx.x * blockDim.y + threadIdx.y;
    int lane = threadIdx.x;
    const float* p = P + (size_t)row * D;
    const float* q = Q + (size_t)row * D;
    float s = p[lane] * p[lane] + p[lane + 32] * p[lane + 32];
    float t = q[lane] * q[lane] + q[lane + 32] * q[lane + 32];
    #pragma unroll
    for (int o = 16; o; o >>= 1) {
        s += __shfl_xor_sync(0xffffffffu, s, o);
        t += __shfl_xor_sync(0xffffffffu, t, o);
    }
    if (lane == 0) { g_sp[row] = s; g_sq[row] = t; }
}

// ---------------------------------------------------------------------------
// 2) build K (bf16) via HMMA mma.sync: 128x128 tile/CTA, 8 warps x (64x32)
//    Also emits deterministic per-(coltile,colwarp) row partial sums of K.
// ---------------------------------------------------------------------------
#define AS_STRIDE 72    // bf16 elements per smem row (conflict-free fragment LDS)
#define CS_STRIDE 136   // bf16 elements per staged output row (conflict-free)

__global__ __launch_bounds__(256) void build_kernel(const float* __restrict__ P,
                                                    const float* __restrict__ Q) {
    __shared__ __align__(16) char sm_raw[2 * 128 * AS_STRIDE * 2];   // 36864 B
    __nv_bfloat16* As = (__nv_bfloat16*)sm_raw;                      // [128][72]
    __nv_bfloat16* Bs = (__nv_bfloat16*)(sm_raw + 128 * AS_STRIDE * 2);
    __nv_bfloat16* Cs = (__nv_bfloat16*)sm_raw;                      // reused: [128][136]

    const int tid  = threadIdx.x;
    const int wid  = tid >> 5;
    const int lane = tid & 31;
    const int r0 = blockIdx.y * 128;
    const int c0 = blockIdx.x * 128;

    // cooperative load + fp32->bf16 convert (coalesced float4 per thread)
    #pragma unroll
    for (int it = 0; it < 8; it++) {
        int idx = tid + it * 256;          // 0..2047
        int r   = idx >> 4;                // 0..127
        int k4  = (idx & 15) << 2;         // 0,4,...,60
        float4 a = *(const float4*)(P + (size_t)(r0 + r) * D + k4);
        float4 b = *(const float4*)(Q + (size_t)(c0 + r) * D + k4);
        __nv_bfloat162 a01 = __floats2bfloat162_rn(a.x, a.y);
        __nv_bfloat162 a23 = __floats2bfloat162_rn(a.z, a.w);
        __nv_bfloat162 b01 = __floats2bfloat162_rn(b.x, b.y);
        __nv_bfloat162 b23 = __floats2bfloat162_rn(b.z, b.w);
        uint2 av, bv;
        av.x = *(uint32_t*)&a01; av.y = *(uint32_t*)&a23;
        bv.x = *(uint32_t*)&b01; bv.y = *(uint32_t*)&b23;
        *(uint2*)(As + r * AS_STRIDE + k4) = av;
        *(uint2*)(Bs + r * AS_STRIDE + k4) = bv;
    }
    __syncthreads();

    const int g = lane >> 2;      // 0..7
    const int t = lane & 3;       // 0..3
    const int wr0 = (wid >> 2) * 64;   // warp row offset in tile
    const int wc0 = (wid & 3) * 32;    // warp col offset in tile

    // acc[mi][ni][reg]: c0=(g,2t) c1=(g,2t+1) c2=(g+8,2t) c3=(g+8,2t+1)
    float acc[4][4][4];
    #pragma unroll
    for (int mi = 0; mi < 4; mi++)
        #pragma unroll
        for (int ni = 0; ni < 4; ni++)
            acc[mi][ni][0] = acc[mi][ni][1] = acc[mi][ni][2] = acc[mi][ni][3] = 0.0f;

    #pragma unroll
    for (int ks = 0; ks < 4; ks++) {
        const int kc = ks * 16 + 2 * t;
        uint32_t af[4][4];
        #pragma unroll
        for (int mi = 0; mi < 4; mi++) {
            const __nv_bfloat16* ar = As + (wr0 + mi * 16 + g) * AS_STRIDE + kc;
            af[mi][0] = *(const uint32_t*)(ar);
            af[mi][1] = *(const uint32_t*)(ar + 8 * AS_STRIDE);
            af[mi][2] = *(const uint32_t*)(ar + 8);
            af[mi][3] = *(const uint32_t*)(ar + 8 * AS_STRIDE + 8);
        }
        uint32_t bf[4][2];
        #pragma unroll
        for (int ni = 0; ni < 4; ni++) {
            const __nv_bfloat16* br = Bs + (wc0 + ni * 8 + g) * AS_STRIDE + kc;
            bf[ni][0] = *(const uint32_t*)(br);
            bf[ni][1] = *(const uint32_t*)(br + 8);
        }
        #pragma unroll
        for (int mi = 0; mi < 4; mi++)
            #pragma unroll
            for (int ni = 0; ni < 4; ni++) {
                asm volatile(
                    "mma.sync.aligned.m16n8k16.row.col.f32.bf16.bf16.f32 "
                    "{%0,%1,%2,%3}, {%4,%5,%6,%7}, {%8,%9}, {%0,%1,%2,%3};"
                    : "+f"(acc[mi][ni][0]), "+f"(acc[mi][ni][1]),
                      "+f"(acc[mi][ni][2]), "+f"(acc[mi][ni][3])
                    : "r"(af[mi][0]), "r"(af[mi][1]), "r"(af[mi][2]), "r"(af[mi][3]),
                      "r"(bf[ni][0]), "r"(bf[ni][1]));
            }
    }
    __syncthreads();   // done reading As/Bs; smem is reused as Cs

    // epilogue: s = max(sp+sq-2*dot, 0); C = sqrt(s); K = ex2(C * -log2e/eps)
    float sp0[4], sp8[4];
    #pragma unroll
    for (int mi = 0; mi < 4; mi++) {
        sp0[mi] = g_sp[r0 + wr0 + mi * 16 + g];
        sp8[mi] = g_sp[r0 + wr0 + mi * 16 + g + 8];
    }
    float sq0[4], sq1[4];
    #pragma unroll
    for (int ni = 0; ni < 4; ni++) {
        sq0[ni] = g_sq[c0 + wc0 + ni * 8 + 2 * t];
        sq1[ni] = g_sq[c0 + wc0 + ni * 8 + 2 * t + 1];
    }

    float rs0[4] = {0.f, 0.f, 0.f, 0.f};   // row partial sums of K (rows g)
    float rs8[4] = {0.f, 0.f, 0.f, 0.f};   // rows g+8

    #pragma unroll
    for (int mi = 0; mi < 4; mi++) {
        #pragma unroll
        for (int ni = 0; ni < 4; ni++) {
            float s00 = fmaxf(sp0[mi] + sq0[ni] - 2.0f * acc[mi][ni][0], 0.0f);
            float s01 = fmaxf(sp0[mi] + sq1[ni] - 2.0f * acc[mi][ni][1], 0.0f);
            float s10 = fmaxf(sp8[mi] + sq0[ni] - 2.0f * acc[mi][ni][2], 0.0f);
            float s11 = fmaxf(sp8[mi] + sq1[ni] - 2.0f * acc[mi][ni][3], 0.0f);
            float k00 = fex2_approx(fsqrt_approx(s00) * NEG_INVEPS_LOG2E);
            float k01 = fex2_approx(fsqrt_approx(s01) * NEG_INVEPS_LOG2E);
            float k10 = fex2_approx(fsqrt_approx(s10) * NEG_INVEPS_LOG2E);
            float k11 = fex2_approx(fsqrt_approx(s11) * NEG_INVEPS_LOG2E);
            rs0[mi] += k00 + k01;
            rs8[mi] += k10 + k11;
            __nv_bfloat162 h0 = __floats2bfloat162_rn(k00, k01);
            __nv_bfloat162 h1 = __floats2bfloat162_rn(k10, k11);
            int col = wc0 + ni * 8 + 2 * t;
            *(uint32_t*)(Cs + (wr0 + mi * 16 + g    ) * CS_STRIDE + col) = *(uint32_t*)&h0;
            *(uint32_t*)(Cs + (wr0 + mi * 16 + g + 8) * CS_STRIDE + col) = *(uint32_t*)&h1;
        }
    }

    // deterministic row-partials: reduce across the 4 t-lanes, write unique slot
    {
        const int slot = blockIdx.x * 4 + (wid & 3);
        #pragma unroll
        for (int mi = 0; mi < 4; mi++) {
            float a = rs0[mi], b = rs8[mi];
            a += __shfl_xor_sync(0xffffffffu, a, 1);
            a += __shfl_xor_sync(0xffffffffu, a, 2);
            b += __shfl_xor_sync(0xffffffffu, b, 1);
            b += __shfl_xor_sync(0xffffffffu, b, 2);
            if (t == 0) {
                g_rowpart[slot][r0 + wr0 + mi * 16 + g]     = a;
                g_rowpart[slot][r0 + wr0 + mi * 16 + g + 8] = b;
            }
        }
    }
    __syncthreads();

    // coalesced bf16 store: 128 rows x 256 B, uint4 per thread
    #pragma unroll
    for (int it = 0; it < 8; it++) {
        int idx = tid + it * 256;          // 0..2047
        int r   = idx >> 4;                // 0..127
        int cc  = (idx & 15) * 8;          // 0..120
        uint4 v = *(const uint4*)(Cs + r * CS_STRIDE + cc);
        *(uint4*)(g_K + (size_t)(r0 + r) * N + (c0 + cc)) = v;
    }
}

// ---------------------------------------------------------------------------
// 2b) v1 = 64 / rowsum(K)   (fixed-order fold of the 256 partials per row)
// ---------------------------------------------------------------------------
__global__ __launch_bounds__(256) void vinit_kernel() {
    int i = blockIdx.x * 256 + threadIdx.x;
    float a0 = 0.f, a1 = 0.f, a2 = 0.f, a3 = 0.f;
    #pragma unroll 8
    for (int p = 0; p < 256; p += 4) {
        a0 += g_rowpart[p + 0][i];
        a1 += g_rowpart[p + 1][i];
        a2 += g_rowpart[p + 2][i];
        a3 += g_rowpart[p + 3][i];
    }
    g_v[i] = 64.0f / ((a0 + a1) + (a2 + a3));
}

// ---------------------------------------------------------------------------
// 3) Sinkhorn matvec: 8 rows/block, x staged in smem.
//    y_i = 1 / sum_j K_ij x_j   (dir=0: u->v, dir=1: v->u)
// ---------------------------------------------------------------------------
__global__ __launch_bounds__(256) void matvec_kernel(int dir) {
    const float* __restrict__ x = dir ? g_v : g_u;
    float*       __restrict__ y = dir ? g_u : g_v;

    __shared__ __align__(16) float xs[N];
    #pragma unroll
    for (int it = 0; it < 8; it++) {
        int j = (threadIdx.x + it * 256) * 4;
        *(float4*)(xs + j) = *(const float4*)(x + j);
    }
    __syncthreads();

    const int lane = threadIdx.x & 31;
    const int row  = blockIdx.x * 8 + (threadIdx.x >> 5);
    const __nv_bfloat16* kr = g_K + (size_t)row * N;

    float s0 = 0.0f, s1 = 0.0f;
    #pragma unroll 4
    for (int it = 0; it < 32; it++) {
        int j = lane * 8 + it * 256;
        uint4  kw = *(const uint4*)(kr + j);
        float4 x0 = *(const float4*)(xs + j);
        float4 x1 = *(const float4*)(xs + j + 4);
        float2 k0 = __bfloat1622float2(*(__nv_bfloat162*)&kw.x);
        float2 k1 = __bfloat1622float2(*(__nv_bfloat162*)&kw.y);
        float2 k2 = __bfloat1622float2(*(__nv_bfloat162*)&kw.z);
        float2 k3 = __bfloat1622float2(*(__nv_bfloat162*)&kw.w);
        s0 = fmaf(k0.x, x0.x, s0); s1 = fmaf(k0.y, x0.y, s1);
        s0 = fmaf(k1.x, x0.z, s0); s1 = fmaf(k1.y, x0.w, s1);
        s0 = fmaf(k2.x, x1.x, s0); s1 = fmaf(k2.y, x1.y, s1);
        s0 = fmaf(k3.x, x1.z, s0); s1 = fmaf(k3.y, x1.w, s1);
    }
    float s = s0 + s1;
    #pragma unroll
    for (int o = 16; o; o >>= 1) s += __shfl_xor_sync(0xffffffffu, s, o);
    if (lane == 0) y[row] = 1.0f / s;
}

// ---------------------------------------------------------------------------
// 4) fused last matvec + loss rows:
//    s1 = sum K v,  s2 = sum K*lg2(K)*v;  part_i = NEG_EPS_LN2 * s2 / s1
//    (u_i = 1/s1 is folded in; C = lg2(K)*(-eps*ln2))
// ---------------------------------------------------------------------------
__global__ __launch_bounds__(256) void final_fused_kernel() {
    __shared__ __align__(16) float xs[N];
    #pragma unroll
    for (int it = 0; it < 8; it++) {
        int j = (threadIdx.x + it * 256) * 4;
        *(float4*)(xs + j) = *(const float4*)(g_v + j);
    }
    __syncthreads();

    const int lane = threadIdx.x & 31;
    const int row  = blockIdx.x * 8 + (threadIdx.x >> 5);
    const __nv_bfloat16* kr = g_K + (size_t)row * N;

    float s1 = 0.0f, s2 = 0.0f;
    #pragma unroll 2
    for (int it = 0; it < 32; it++) {
        int j = lane * 8 + it * 256;
        uint4  kw = *(const uint4*)(kr + j);
        float4 x0 = *(const float4*)(xs + j);
        float4 x1 = *(const float4*)(xs + j + 4);
        float2 k0 = __bfloat1622float2(*(__nv_bfloat162*)&kw.x);
        float2 k1 = __bfloat1622float2(*(__nv_bfloat162*)&kw.y);
        float2 k2 = __bfloat1622float2(*(__nv_bfloat162*)&kw.z);
        float2 k3 = __bfloat1622float2(*(__nv_bfloat162*)&kw.w);
        float kv;
        kv = k0.x * x0.x; s1 += kv; s2 = fmaf(kv, flg2_approx(k0.x), s2);
        kv = k0.y * x0.y; s1 += kv; s2 = fmaf(kv, flg2_approx(k0.y), s2);
        kv = k1.x * x0.z; s1 += kv; s2 = fmaf(kv, flg2_approx(k1.x), s2);
        kv = k1.y * x0.w; s1 += kv; s2 = fmaf(kv, flg2_approx(k1.y), s2);
        kv = k2.x * x1.x; s1 += kv; s2 = fmaf(kv, flg2_approx(k2.x), s2);
        kv = k2.y * x1.y; s1 += kv; s2 = fmaf(kv, flg2_approx(k2.y), s2);
        kv = k3.x * x1.z; s1 += kv; s2 = fmaf(kv, flg2_approx(k3.x), s2);
        kv = k3.y * x1.w; s1 += kv; s2 = fmaf(kv, flg2_approx(k3.y), s2);
    }
    #pragma unroll
    for (int o = 16; o; o >>= 1) {
        s1 += __shfl_xor_sync(0xffffffffu, s1, o);
        s2 += __shfl_xor_sync(0xffffffffu, s2, o);
    }
    if (lane == 0) g_part[row] = NEG_EPS_LN2 * s2 / s1;
}

// 5) deterministic scalar reduce (double accumulation, fixed tree order)
__global__ void reduce_kernel(float* __restrict__ out) {
    __shared__ double sh[256];
    double s = 0.0;
    for (int i = threadIdx.x; i < N; i += 256) s += (double)g_part[i];
    sh[threadIdx.x] = s;
    __syncthreads();
    for (int o = 128; o; o >>= 1) {
        if (threadIdx.x < o) sh[threadIdx.x] += sh[threadIdx.x + o];
        __syncthreads();
    }
    if (threadIdx.x == 0) out[0] = (float)sh[0];
}

// ---------------------------------------------------------------------------
extern "C" void kernel_launch(void* const* d_in, const int* in_sizes, int n_in,
                              void* d_out, int out_size) {
    const float* P = (const float*)d_in[0];
    const float* Q = (const float*)d_in[1];
    float* out = (float*)d_out;

    norms_kernel<<<N / 8, dim3(32, 8)>>>(P, Q);

    dim3 grid(N / 128, N / 128);
    build_kernel<<<grid, 256>>>(P, Q);     // also emits row partials of K

    vinit_kernel<<<N / 256, 256>>>();      // iter1: v = 64 / rowsum  (free pass)

    matvec_kernel<<<N / 8, 256>>>(1);      // iter1: u = 1/(K v)
    for (int it = 0; it < 3; it++) {       // iters 2-4
        matvec_kernel<<<N / 8, 256>>>(0);  // v = 1/(K u)
        matvec_kernel<<<N / 8, 256>>>(1);  // u = 1/(K v)
    }
    matvec_kernel<<<N / 8, 256>>>(0);      // iter5: v = 1/(K u)

    final_fused_kernel<<<N / 8, 256>>>();  // iter5 u folded into loss rows
    reduce_kernel<<<1, 256>>>(out);
}